// round 6
// baseline (speedup 1.0000x reference)
#include <cuda_runtime.h>
#include <cstdint>

#define NN 10000
#define EE 100000

// ---------------- device scratch (static allocations only) ----------------
__device__ __align__(16) float g_v[NN * 2048];   // v[n][j*64+o]  82 MB
__device__ __align__(16) float g_u[NN * 64];
__device__ __align__(16) float g_r[NN * 64];
__device__ __align__(16) float g_agg[NN * 64];   // zeroed at end of k_node (self-restoring)
__device__ __align__(16) float g_h[EE * 32];     // relu(ea@w1+b1)  12.8 MB
__device__ int g_histsrc[NN];                    // zeroed inside k_scan after read
__device__ int g_cntdst[NN];                     // zeroed at end of k_node
__device__ int g_start[NN + 1];
__device__ int g_cursor[NN];
__device__ int g_order[EE];
__device__ int g_odst[EE];
__device__ __align__(16) float g_A[64 * 64];
__device__ __align__(16) float g_B[64 * 64];
__device__ __align__(16) float g_C[64 * 64];
__device__ __align__(16) float g_dv[64];

// ---------------- tf32 helpers ----------------
__device__ __forceinline__ void tf32_split(float f, unsigned& hi, unsigned& lo) {
    asm("cvt.rna.tf32.f32 %0, %1;" : "=r"(hi) : "f"(f));
    float l = f - __uint_as_float(hi);
    asm("cvt.rna.tf32.f32 %0, %1;" : "=r"(lo) : "f"(l));
}

__device__ __forceinline__ void mma_tf32(float* acc, const unsigned* a, unsigned b0, unsigned b1) {
    asm volatile(
        "mma.sync.aligned.m16n8k8.row.col.f32.tf32.tf32.f32 "
        "{%0,%1,%2,%3}, {%4,%5,%6,%7}, {%8,%9}, {%0,%1,%2,%3};"
        : "+f"(acc[0]), "+f"(acc[1]), "+f"(acc[2]), "+f"(acc[3])
        : "r"(a[0]), "r"(a[1]), "r"(a[2]), "r"(a[3]), "r"(b0), "r"(b1));
}

// ---------------- launch 1: histogram ----------------
__global__ void k_hist(const int* __restrict__ ei) {
    int e = blockIdx.x * 256 + threadIdx.x;
    if (e < EE) {
        atomicAdd(&g_histsrc[ei[e]], 1);
        atomicAdd(&g_cntdst[ei[EE + e]], 1);
    }
}

// ---------------- launch 2: exclusive scan over 10000 src counts ----------------
__global__ void k_scan() {
    __shared__ int sums[1024];
    int t = threadIdx.x;
    const int CH = 10;
    int base = t * CH;
    int loc[CH];
    int s = 0;
#pragma unroll
    for (int k = 0; k < CH; k++) {
        int idx = base + k;
        int v = 0;
        if (idx < NN) { v = g_histsrc[idx]; g_histsrc[idx] = 0; }
        loc[k] = s; s += v;
    }
    sums[t] = s;
    __syncthreads();
    for (int off = 1; off < 1024; off <<= 1) {
        int v = sums[t];
        int u = (t >= off) ? sums[t - off] : 0;
        __syncthreads();
        sums[t] = v + u;
        __syncthreads();
    }
    int excl = (t > 0) ? sums[t - 1] : 0;
#pragma unroll
    for (int k = 0; k < CH; k++) {
        int idx = base + k;
        if (idx < NN) {
            int st = excl + loc[k];
            g_start[idx] = st;
            g_cursor[idx] = st;
        }
    }
    if (t == 1023) g_start[NN] = sums[1023];
}

// ---------------- launch 3: fused independent mid work ----------------
// block ranges: scatter | v-MMA | H-GEMM | ur-GEMM | prep
#define MB_SC   391
#define MB_V    (MB_SC + 2528)      // 79 node-chunks x 32 col-tiles
#define MB_H    (MB_V + 1563)
#define MB_UR   (MB_H + 157)
#define MB_P    (MB_UR + 16)

__global__ void __launch_bounds__(256) k_mid(
    const float* __restrict__ x,  const float* __restrict__ w2,
    const float* __restrict__ b2, const float* __restrict__ root,
    const float* __restrict__ ea, const float* __restrict__ w1,
    const float* __restrict__ b1, const int* __restrict__ ei,
    const float* __restrict__ tw1, const float* __restrict__ tb1,
    const float* __restrict__ tw2, const float* __restrict__ tb2,
    const float* __restrict__ tw3, const float* __restrict__ tb3,
    const float* __restrict__ pw,  const float* __restrict__ pb) {
    __shared__ __align__(16) float sbuf[6912];      // 27.6 KB union
    int b = blockIdx.x;
    int t = threadIdx.x;

    if (b < MB_SC) {
        // ---- scatter edge ids grouped by src; also record dst ----
        int e = b * 256 + t;
        if (e < EE) {
            int s = ei[e];
            int pos = atomicAdd(&g_cursor[s], 1);
            g_order[pos] = e;
            g_odst[pos] = ei[EE + e];
        }
    } else if (b < MB_V) {
        // ---- v via 3xTF32 mma: block = 128 nodes x 64 cols ----
        int vb = b - MB_SC;
        int ct = vb & 31;                  // col tile [0,32): cols ct*64..+64
        int nb = (vb >> 5) * 128;          // node chunk base
        float* xs = sbuf;                  // [128][36] raw fp32, padded
        float* ws = sbuf + 128 * 36;       // [32][72]  raw fp32, padded

        for (int q = t; q < 128 * 32; q += 256) {
            int n = q >> 5, i = q & 31;
            xs[n * 36 + i] = (nb + n < NN) ? x[(nb + n) * 32 + i] : 0.f;
        }
        for (int q = t; q < 2048; q += 256) {
            int i = q >> 6, cc = q & 63;
            ws[i * 72 + cc] = w2[ct * 2048 + i * 64 + cc];
        }
        __syncthreads();

        int w = t >> 5, l = t & 31;
        int r0 = w * 16 + (l >> 2);        // local node row of a0/a2 (a1/a3: +8)
        int cA = l & 3;

        float acc[8][4];
#pragma unroll
        for (int nt = 0; nt < 8; nt++)
#pragma unroll
            for (int q = 0; q < 4; q++) acc[nt][q] = 0.f;

#pragma unroll
        for (int ks = 0; ks < 4; ks++) {
            int k0 = ks * 8;
            float a0f = xs[r0 * 36 + k0 + cA];
            float a1f = xs[(r0 + 8) * 36 + k0 + cA];
            float a2f = xs[r0 * 36 + k0 + cA + 4];
            float a3f = xs[(r0 + 8) * 36 + k0 + cA + 4];
            unsigned ah[4], al[4];
            tf32_split(a0f, ah[0], al[0]);
            tf32_split(a1f, ah[1], al[1]);
            tf32_split(a2f, ah[2], al[2]);
            tf32_split(a3f, ah[3], al[3]);
#pragma unroll
            for (int nt = 0; nt < 8; nt++) {
                float b0f = ws[(k0 + cA) * 72 + nt * 8 + (l >> 2)];
                float b1f = ws[(k0 + cA + 4) * 72 + nt * 8 + (l >> 2)];
                unsigned bh0, bl0, bh1, bl1;
                tf32_split(b0f, bh0, bl0);
                tf32_split(b1f, bh1, bl1);
                mma_tf32(acc[nt], ah, bh0, bh1);   // hi*hi
                mma_tf32(acc[nt], ah, bl0, bl1);   // hi*lo
                mma_tf32(acc[nt], al, bh0, bh1);   // lo*hi
            }
        }

#pragma unroll
        for (int nt = 0; nt < 8; nt++) {
            int colb = ct * 64 + nt * 8 + 2 * cA;
            int n0 = nb + r0;
            if (n0 < NN)
                *(float2*)&g_v[n0 * 2048 + colb] = make_float2(acc[nt][0], acc[nt][1]);
            int n1 = n0 + 8;
            if (n1 < NN)
                *(float2*)&g_v[n1 * 2048 + colb] = make_float2(acc[nt][2], acc[nt][3]);
        }
    } else if (b < MB_H) {
        // ---- H GEMM: g_h[e][j] = relu(sum_d ea[e,d]*w1[d,j] + b1[j]) ----
        int base = (b - MB_V) * 64;
        float* eas = sbuf;                       // [64*16]
        float* w1s = eas + 1024;                 // [512]
        float* b1s = w1s + 512;                  // [32]
        for (int q = t; q < 1024; q += 256) {
            int gidx = base * 16 + q;
            eas[q] = (gidx < EE * 16) ? ea[gidx] : 0.f;
        }
        for (int q = t; q < 512; q += 256) w1s[q] = w1[q];
        if (t < 32) b1s[t] = b1[t];
        __syncthreads();
        for (int q = t; q < 2048; q += 256) {
            int el = q >> 5, j = q & 31;
            int e = base + el;
            if (e < EE) {
                float acc = b1s[j];
#pragma unroll
                for (int d = 0; d < 16; d++)
                    acc = fmaf(eas[el * 16 + d], w1s[d * 32 + j], acc);
                g_h[e * 32 + j] = fmaxf(acc, 0.f);
            }
        }
    } else if (b < MB_UR) {
        // ---- u/r GEMM: [64 nodes] x [128 cols: u(64)|r(64)] ----
        int nb = (b - MB_H) * 64;
        float4* Wc = (float4*)sbuf;               // [i*32 + c4], c4<16: b2, else root
        float*  xT = sbuf + 4096;                 // [i*64 + n]
        const float4* b2f4 = (const float4*)b2;
        const float4* rtf4 = (const float4*)root;
#pragma unroll
        for (int q = 0; q < 4; q++) {
            int idx = q * 256 + t;                // [0,1024)
            int i = idx >> 5, c4 = idx & 31;
            Wc[idx] = (c4 < 16) ? b2f4[i * 16 + c4] : rtf4[i * 16 + (c4 - 16)];
        }
#pragma unroll
        for (int q = 0; q < 8; q++) {
            int f = q * 256 + t;
            int n = f >> 5, i = f & 31;
            xT[i * 64 + n] = (nb + n < NN) ? x[(nb + n) * 32 + i] : 0.f;
        }
        __syncthreads();

        int ng = t >> 5, cg = t & 31;
        float acc[8][4];
#pragma unroll
        for (int a = 0; a < 8; a++)
#pragma unroll
            for (int c = 0; c < 4; c++) acc[a][c] = 0.f;

#pragma unroll 8
        for (int i = 0; i < 32; i++) {
            float4 xa = *(const float4*)&xT[i * 64 + ng * 8];
            float4 xb = *(const float4*)&xT[i * 64 + ng * 8 + 4];
            float4 w = Wc[i * 32 + cg];
            float xv[8] = {xa.x, xa.y, xa.z, xa.w, xb.x, xb.y, xb.z, xb.w};
            float wv[4] = {w.x, w.y, w.z, w.w};
#pragma unroll
            for (int a = 0; a < 8; a++)
#pragma unroll
                for (int c = 0; c < 4; c++) acc[a][c] = fmaf(xv[a], wv[c], acc[a][c]);
        }

        float4* u4 = (float4*)g_u;
        float4* r4 = (float4*)g_r;
#pragma unroll
        for (int a = 0; a < 8; a++) {
            int n = nb + ng * 8 + a;
            if (n < NN) {
                float4 val = make_float4(acc[a][0], acc[a][1], acc[a][2], acc[a][3]);
                if (cg < 16) u4[n * 16 + cg] = val;
                else         r4[n * 16 + (cg - 16)] = val;
            }
        }
    } else {
        // ---- prep: fold TCN+proj into A,B,C,dv ----
        int q = (b - MB_UR) * 256 + t;            // [0,4096)
        int c = q >> 6, p = q & 63;
        float a = 0.f, bb = 0.f, cc = 0.f;
        for (int o = 0; o < 64; o++) {
            float pw0 = __ldg(&pw[o * 64 + p]);
            float pw1 = __ldg(&pw[(64 + o) * 64 + p]);
            float pw2 = __ldg(&pw[(128 + o) * 64 + p]);
            bb = fmaf(__ldg(&tw1[o * 192 + c * 3 + 0]), pw0, bb);
            a  = fmaf(__ldg(&tw2[o * 192 + c * 3 + 0]), pw1, a);
            cc = fmaf(__ldg(&tw1[o * 192 + c * 3 + 1]), pw0, cc);
            cc = fmaf(__ldg(&tw2[o * 192 + c * 3 + 1]), pw1, cc);
            cc = fmaf(__ldg(&tw3[o * 192 + c * 3 + 1]), pw2, cc);
        }
        g_A[q] = a; g_B[q] = bb; g_C[q] = cc;
        if (b == MB_UR && t < 64) {
            float d = pb[t];
            for (int o = 0; o < 64; o++) {
                d = fmaf(tb1[o], pw[o * 64 + t], d);
                d = fmaf(tb2[o], pw[(64 + o) * 64 + t], d);
                d = fmaf(tb3[o], pw[(128 + o) * 64 + t], d);
            }
            g_dv[t] = d;
        }
    }
}

// ---------------- launch 4: edge kernel — 2 warps per node, depth-2 prefetch ----------------
__global__ void __launch_bounds__(128) k_edge() {
    int t = threadIdx.x;
    int w = t >> 5, l = t & 31;
    int n = blockIdx.x * 2 + (w >> 1);        // grid 5000 -> exactly NN
    int half = w & 1;
    int col = half * 32 + l;
    int beg = g_start[n], end = g_start[n + 1];
    if (beg == end) return;

    const float* vbase = g_v + n * 2048 + col;
    float vreg[32];
#pragma unroll
    for (int j = 0; j < 32; j++) vreg[j] = __ldg(&vbase[j * 64]);
    float u = __ldg(&g_u[n * 64 + col]);

    float h0 = __ldg(&g_h[g_order[beg] * 32 + l]);
    float h1 = (beg + 1 < end) ? __ldg(&g_h[g_order[beg + 1] * 32 + l]) : 0.f;

    for (int p = beg; p < end; p++) {
        int dn = g_odst[p];
        float h2 = (p + 2 < end) ? __ldg(&g_h[g_order[p + 2] * 32 + l]) : 0.f;
        float m0 = u, m1 = 0.f, m2 = 0.f, m3 = 0.f;
#pragma unroll
        for (int j = 0; j < 32; j += 4) {
            float a0 = __shfl_sync(0xffffffffu, h0, j);
            float a1 = __shfl_sync(0xffffffffu, h0, j + 1);
            float a2 = __shfl_sync(0xffffffffu, h0, j + 2);
            float a3 = __shfl_sync(0xffffffffu, h0, j + 3);
            m0 = fmaf(a0, vreg[j],     m0);
            m1 = fmaf(a1, vreg[j + 1], m1);
            m2 = fmaf(a2, vreg[j + 2], m2);
            m3 = fmaf(a3, vreg[j + 3], m3);
        }
        float m = (m0 + m1) + (m2 + m3);
        asm volatile("red.global.add.f32 [%0], %1;"
                     :: "l"(g_agg + dn * 64 + col), "f"(m) : "memory");
        h0 = h1; h1 = h2;
    }
}

// ---------------- launch 5: node kernel ----------------
__global__ void k_node(const float* __restrict__ hprev, const float* __restrict__ bias,
                       float* __restrict__ hout, float* __restrict__ hhist) {
    __shared__ float hs0[64 * 52];
    __shared__ float hs1[64 * 52];
    __shared__ float hs2[64 * 52];
    int t = threadIdx.x;              // 192 threads
    int nb = blockIdx.x * 48;

    for (int s = 0; s < 16; s++) {
        int q = s * 192 + t;
        int nl = q >> 6, o = q & 63;
        int n = nb + nl;
        float hp1 = 0.f, hp2 = 0.f, hg = 0.f;
        if (n < NN) {
            hp1 = hprev[n * 192 + 64 + o];
            hp2 = hprev[n * 192 + 128 + o];
            float cnt = (float)g_cntdst[n];
            float mean = g_agg[n * 64 + o] / fmaxf(cnt, 1.f);
            hg = fmaxf(mean + g_r[n * 64 + o] + bias[o], 0.f);
            hhist[n * 192 + o] = hp1;
            hhist[n * 192 + 64 + o] = hp2;
            hhist[n * 192 + 128 + o] = hg;
        }
        hs0[o * 52 + nl] = hp1;
        hs1[o * 52 + nl] = hp2;
        hs2[o * 52 + nl] = hg;
    }
    __syncthreads();

    // restore invariants for next replay
    for (int q = t; q < 48 * 64; q += 192) {
        int n = nb + (q >> 6);
        if (n < NN) g_agg[n * 64 + (q & 63)] = 0.f;
    }
    if (t < 48 && nb + t < NN) g_cntdst[nb + t] = 0;

    int tn = t % 12, tp = t / 12;
    int n0 = tn * 4, p0 = tp * 4;
    float4 dv = *(const float4*)&g_dv[p0];
    float acc[4][4];
#pragma unroll
    for (int a = 0; a < 4; a++) {
        acc[a][0] = dv.x; acc[a][1] = dv.y; acc[a][2] = dv.z; acc[a][3] = dv.w;
    }

#pragma unroll 8
    for (int c = 0; c < 64; c++) {
        float4 h0 = *(const float4*)&hs0[c * 52 + n0];
        float4 h1 = *(const float4*)&hs1[c * 52 + n0];
        float4 h2 = *(const float4*)&hs2[c * 52 + n0];
        float4 av = __ldg((const float4*)(g_A + c * 64 + p0));
        float4 bv = __ldg((const float4*)(g_B + c * 64 + p0));
        float4 cv = __ldg((const float4*)(g_C + c * 64 + p0));
        float h0v[4] = {h0.x, h0.y, h0.z, h0.w};
        float h1v[4] = {h1.x, h1.y, h1.z, h1.w};
        float h2v[4] = {h2.x, h2.y, h2.z, h2.w};
        float avv[4] = {av.x, av.y, av.z, av.w};
        float bvv[4] = {bv.x, bv.y, bv.z, bv.w};
        float cvv[4] = {cv.x, cv.y, cv.z, cv.w};
#pragma unroll
        for (int a = 0; a < 4; a++)
#pragma unroll
            for (int c2 = 0; c2 < 4; c2++) {
                acc[a][c2] = fmaf(h0v[a], avv[c2], acc[a][c2]);
                acc[a][c2] = fmaf(h1v[a], bvv[c2], acc[a][c2]);
                acc[a][c2] = fmaf(h2v[a], cvv[c2], acc[a][c2]);
            }
    }

#pragma unroll
    for (int a = 0; a < 4; a++) {
        int n = nb + n0 + a;
        if (n < NN)
            *(float4*)&hout[n * 64 + p0] = make_float4(acc[a][0], acc[a][1], acc[a][2], acc[a][3]);
    }
}

// ---------------- launch ----------------
extern "C" void kernel_launch(void* const* d_in, const int* in_sizes, int n_in,
                              void* d_out, int out_size) {
    const float* x     = (const float*)d_in[0];
    const float* ea    = (const float*)d_in[1];
    const float* hprev = (const float*)d_in[2];
    const int*   ei    = (const int*)  d_in[3];
    const float* w1    = (const float*)d_in[4];
    const float* b1    = (const float*)d_in[5];
    const float* w2    = (const float*)d_in[6];
    const float* b2    = (const float*)d_in[7];
    const float* root  = (const float*)d_in[8];
    const float* bias  = (const float*)d_in[9];
    const float* tw1   = (const float*)d_in[10];
    const float* tb1   = (const float*)d_in[11];
    const float* tw2   = (const float*)d_in[12];
    const float* tb2   = (const float*)d_in[13];
    const float* tw3   = (const float*)d_in[14];
    const float* tb3   = (const float*)d_in[15];
    const float* pw    = (const float*)d_in[16];
    const float* pb    = (const float*)d_in[17];

    float* hout  = (float*)d_out;            // [N,64]
    float* hhist = hout + NN * 64;           // [N,3,64]

    k_hist<<<(EE + 255) / 256, 256>>>(ei);
    k_scan<<<1, 1024>>>();
    k_mid<<<MB_P, 256>>>(x, w2, b2, root, ea, w1, b1, ei,
                         tw1, tb1, tw2, tb2, tw3, tb3, pw, pb);
    k_edge<<<5000, 128>>>();
    k_node<<<209, 192>>>(hprev, bias, hout, hhist);
}